// round 4
// baseline (speedup 1.0000x reference)
#include <cuda_runtime.h>
#include <math.h>

// ---------------- problem constants ----------------
#define TT   50
#define BB   2048
#define SST  256      // STATE
#define AAC  32       // ACTION
#define BEL  1024     // BELIEF
#define HID  1024     // HIDDEN
#define EMB  1024     // EMBED

// ---------------- scratch (device globals; no allocation allowed) ----------------
__device__ __align__(16) float g_rnn_in[BB * BEL];
__device__ __align__(16) float g_gi[BB * 3 * BEL];
__device__ __align__(16) float g_gh[BB * 3 * BEL];
__device__ __align__(16) float g_ph[BB * HID];
__device__ __align__(16) float g_pout[BB * 2 * SST];
__device__ __align__(16) float g_qh[BB * HID];
__device__ __align__(16) float g_qout[BB * 2 * SST];

// ---------------------------------------------------------------------------
// Generic TN SGEMM:  C[M,N] = act( [A0 | A1] @ W^T + bias )
//   A0: [M, K0] row-major (lda0), A1: [M, K1] row-major (lda1) or null
//   W : [N, K0+K1] row-major with row stride ldw
// Requires: M % BM == 0, N % BN == 0, K0 % BK == 0, (K0+K1) % BK == 0,
//           BM == BN == 256/(BK/4)   (one float4 per thread per tile)
// ---------------------------------------------------------------------------
template <int BM, int BN, int BK, int TM, int TN, bool RELU>
__global__ __launch_bounds__(256)
void gemm_k(const float* __restrict__ A0, int K0, int lda0,
            const float* __restrict__ A1, int K1, int lda1,
            const float* __restrict__ W, int ldw,
            const float* __restrict__ bias,
            float* __restrict__ C, int N)
{
    static_assert(BM * BK == 256 * 4, "A tile = 256 float4");
    static_assert(BN * BK == 256 * 4, "W tile = 256 float4");
    static_assert(TM % 4 == 0 && TN % 4 == 0, "float4 frags");

    __shared__ float As[BK][BM];
    __shared__ float Ws[BK][BN];

    const int tid  = threadIdx.x;
    const int tx   = tid % (BN / TN);
    const int ty   = tid / (BN / TN);
    const int row0 = blockIdx.y * BM;
    const int col0 = blockIdx.x * BN;

    // loader mapping: one float4 per thread per tile
    const int lrow = tid / (BK / 4);
    const int lkc  = (tid % (BK / 4)) * 4;

    float acc[TM][TN];
#pragma unroll
    for (int i = 0; i < TM; i++)
#pragma unroll
        for (int j = 0; j < TN; j++) acc[i][j] = 0.0f;

    const int K = K0 + K1;
    for (int kk = 0; kk < K; kk += BK) {
        // ---- load A tile (source select: whole BK-tile lives in one source) ----
        const float* Asrc;
        int kloc, lda;
        if (kk < K0) { Asrc = A0; kloc = kk;       lda = lda0; }
        else         { Asrc = A1; kloc = kk - K0;  lda = lda1; }
        float4 av = *(const float4*)(Asrc + (size_t)(row0 + lrow) * lda + kloc + lkc);
        As[lkc + 0][lrow] = av.x;
        As[lkc + 1][lrow] = av.y;
        As[lkc + 2][lrow] = av.z;
        As[lkc + 3][lrow] = av.w;

        // ---- load W tile ----
        float4 wv = *(const float4*)(W + (size_t)(col0 + lrow) * ldw + kk + lkc);
        Ws[lkc + 0][lrow] = wv.x;
        Ws[lkc + 1][lrow] = wv.y;
        Ws[lkc + 2][lrow] = wv.z;
        Ws[lkc + 3][lrow] = wv.w;

        __syncthreads();

#pragma unroll
        for (int k = 0; k < BK; k++) {
            float a[TM], b[TN];
#pragma unroll
            for (int i = 0; i < TM; i += 4) {
                float4 t = *(const float4*)&As[k][ty * TM + i];
                a[i] = t.x; a[i + 1] = t.y; a[i + 2] = t.z; a[i + 3] = t.w;
            }
#pragma unroll
            for (int j = 0; j < TN; j += 4) {
                float4 t = *(const float4*)&Ws[k][tx * TN + j];
                b[j] = t.x; b[j + 1] = t.y; b[j + 2] = t.z; b[j + 3] = t.w;
            }
#pragma unroll
            for (int i = 0; i < TM; i++)
#pragma unroll
                for (int j = 0; j < TN; j++)
                    acc[i][j] += a[i] * b[j];
        }
        __syncthreads();
    }

    // ---- epilogue: bias (+ relu) ----
#pragma unroll
    for (int i = 0; i < TM; i++) {
        const int r = row0 + ty * TM + i;
        float* crow = C + (size_t)r * N + col0 + tx * TN;
#pragma unroll
        for (int j = 0; j < TN; j++) {
            float v = acc[i][j] + bias[col0 + tx * TN + j];
            if (RELU) v = fmaxf(v, 0.0f);
            crow[j] = v;
        }
    }
}

// ---------------------------------------------------------------------------
// GRU combine: r = sig(ir+hr), z = sig(iz+hz), n = tanh(in + r*hn),
//              h' = (1-z)*n + z*h
// ---------------------------------------------------------------------------
__global__ void gru_combine(const float* __restrict__ gi,
                            const float* __restrict__ gh,
                            const float* __restrict__ hprev,
                            float* __restrict__ hout)
{
    int i = blockIdx.x * blockDim.x + threadIdx.x;
    if (i >= BB * BEL) return;
    int b = i / BEL;
    int c = i - b * BEL;
    const float* gib = gi + (size_t)b * 3 * BEL;
    const float* ghb = gh + (size_t)b * 3 * BEL;
    float ir = gib[c],           hr = ghb[c];
    float iz = gib[BEL + c],     hz = ghb[BEL + c];
    float in = gib[2 * BEL + c], hn = ghb[2 * BEL + c];
    float r = 1.0f / (1.0f + expf(-(ir + hr)));
    float z = 1.0f / (1.0f + expf(-(iz + hz)));
    float n = tanhf(in + r * hn);
    float h = hprev[i];
    hout[i] = (1.0f - z) * n + z * h;
}

// ---------------------------------------------------------------------------
// Head epilogue: mean = hout[:, :S]; std = softplus(exp(hout[:, S:])) + 0.1
//                state = mean + std * noise
// ---------------------------------------------------------------------------
__global__ void head_epi(const float* __restrict__ hout,   // [B, 2S]
                         const float* __restrict__ noise,  // [B, S]
                         float* __restrict__ o_state,
                         float* __restrict__ o_mean,
                         float* __restrict__ o_std)
{
    int i = blockIdx.x * blockDim.x + threadIdx.x;
    if (i >= BB * SST) return;
    int b = i / SST;
    int c = i - b * SST;
    float m  = hout[(size_t)b * 2 * SST + c];
    float lg = hout[(size_t)b * 2 * SST + SST + c];
    float y  = expf(lg);
    float sp = (y > 20.0f) ? y : log1pf(expf(y));
    float sd = sp + 0.1f;
    o_mean[i]  = m;
    o_std[i]   = sd;
    o_state[i] = m + sd * noise[i];
}

// ---------------------------------------------------------------------------
// host-side dispatch helpers
// ---------------------------------------------------------------------------
static inline void gemm_big(const float* A0, int K0, int lda0,
                            const float* A1, int K1, int lda1,
                            const float* W, int ldw, const float* bias,
                            float* C, int N, bool relu)
{
    dim3 grid(N / 128, BB / 128);
    if (relu)
        gemm_k<128, 128, 8, 8, 8, true ><<<grid, 256>>>(A0, K0, lda0, A1, K1, lda1, W, ldw, bias, C, N);
    else
        gemm_k<128, 128, 8, 8, 8, false><<<grid, 256>>>(A0, K0, lda0, A1, K1, lda1, W, ldw, bias, C, N);
}

static inline void gemm_small(const float* A0, int K0, int lda0,
                              const float* W, int ldw, const float* bias,
                              float* C, int N)
{
    dim3 grid(N / 64, BB / 64);
    gemm_k<64, 64, 16, 4, 4, false><<<grid, 256>>>(A0, K0, lda0, nullptr, 0, 0, W, ldw, bias, C, N);
}

extern "C" void kernel_launch(void* const* d_in, const int* in_sizes, int n_in,
                              void* d_out, int out_size)
{
    // inputs (metadata order = setup_inputs dict order)
    const float* prev_state   = (const float*)d_in[0];   // [B, 256]
    const float* actions      = (const float*)d_in[1];   // [T, B, 32]
    const float* prev_belief  = (const float*)d_in[2];   // [B, 1024]
    const float* observations = (const float*)d_in[3];   // [T, B, 1024]
    const float* prior_noise  = (const float*)d_in[4];   // [T, B, 256]
    const float* post_noise   = (const float*)d_in[5];   // [T, B, 256]
    const float* W_sa = (const float*)d_in[6];           // [1024, 288]
    const float* b_sa = (const float*)d_in[7];
    const float* W_ih = (const float*)d_in[8];           // [3072, 1024]
    const float* W_hh = (const float*)d_in[9];           // [3072, 1024]
    const float* b_ih = (const float*)d_in[10];
    const float* b_hh = (const float*)d_in[11];
    const float* W_pb = (const float*)d_in[12];          // [1024, 1024]
    const float* b_pb = (const float*)d_in[13];
    const float* W_ps = (const float*)d_in[14];          // [512, 1024]
    const float* b_ps = (const float*)d_in[15];
    const float* W_qb = (const float*)d_in[16];          // [1024, 2048]
    const float* b_qb = (const float*)d_in[17];
    const float* W_qs = (const float*)d_in[18];          // [512, 1024]
    const float* b_qs = (const float*)d_in[19];

    // outputs, in reference tuple order
    float* out = (float*)d_out;
    float* out_bel  = out;                               // [T, B, 1024]
    float* out_ps   = out_bel  + (size_t)TT * BB * BEL;  // prior_states  [T,B,256]
    float* out_pm   = out_ps   + (size_t)TT * BB * SST;  // prior_means
    float* out_pstd = out_pm   + (size_t)TT * BB * SST;  // prior_stds
    float* out_qs   = out_pstd + (size_t)TT * BB * SST;  // post_states
    float* out_qm   = out_qs   + (size_t)TT * BB * SST;  // post_means
    float* out_qstd = out_qm   + (size_t)TT * BB * SST;  // post_stds

    // scratch addresses (symbol lookup only; no allocation, capture-safe)
    float *rnn_in, *gi, *gh, *ph, *pout, *qh, *qout;
    cudaGetSymbolAddress((void**)&rnn_in, g_rnn_in);
    cudaGetSymbolAddress((void**)&gi,     g_gi);
    cudaGetSymbolAddress((void**)&gh,     g_gh);
    cudaGetSymbolAddress((void**)&ph,     g_ph);
    cudaGetSymbolAddress((void**)&pout,   g_pout);
    cudaGetSymbolAddress((void**)&qh,     g_qh);
    cudaGetSymbolAddress((void**)&qout,   g_qout);

    const int EW_T = 256;
    const int nb_bel  = (BB * BEL + EW_T - 1) / EW_T;
    const int nb_head = (BB * SST + EW_T - 1) / EW_T;

    for (int t = 0; t < TT; t++) {
        const float* belief_prev = (t == 0) ? prev_belief
                                            : out_bel + (size_t)(t - 1) * BB * BEL;
        const float* state_prev  = (t == 0) ? prev_state
                                            : out_qs  + (size_t)(t - 1) * BB * SST;
        const float* a_t  = actions      + (size_t)t * BB * AAC;
        const float* o_t  = observations + (size_t)t * BB * EMB;
        const float* pn_t = prior_noise  + (size_t)t * BB * SST;
        const float* qn_t = post_noise   + (size_t)t * BB * SST;
        float* bel_t = out_bel + (size_t)t * BB * BEL;

        // 1. rnn_in = relu([post_state, a_t] @ W_sa^T + b_sa)
        gemm_big(state_prev, SST, SST, a_t, AAC, AAC,
                 W_sa, SST + AAC, b_sa, rnn_in, BEL, true);

        // 2. GRU gates
        gemm_big(rnn_in, BEL, BEL, nullptr, 0, 0, W_ih, BEL, b_ih, gi, 3 * BEL, false);
        gemm_big(belief_prev, BEL, BEL, nullptr, 0, 0, W_hh, BEL, b_hh, gh, 3 * BEL, false);
        gru_combine<<<nb_bel, EW_T>>>(gi, gh, belief_prev, bel_t);

        // 3. prior head
        gemm_big(bel_t, BEL, BEL, nullptr, 0, 0, W_pb, BEL, b_pb, ph, HID, true);
        gemm_small(ph, HID, HID, W_ps, HID, b_ps, pout, 2 * SST);
        head_epi<<<nb_head, EW_T>>>(pout, pn_t,
                                    out_ps   + (size_t)t * BB * SST,
                                    out_pm   + (size_t)t * BB * SST,
                                    out_pstd + (size_t)t * BB * SST);

        // 4. posterior head (obs part folded in as second A source)
        gemm_big(bel_t, BEL, BEL, o_t, EMB, EMB,
                 W_qb, BEL + EMB, b_qb, qh, HID, true);
        gemm_small(qh, HID, HID, W_qs, HID, b_qs, qout, 2 * SST);
        head_epi<<<nb_head, EW_T>>>(qout, qn_t,
                                    out_qs   + (size_t)t * BB * SST,
                                    out_qm   + (size_t)t * BB * SST,
                                    out_qstd + (size_t)t * BB * SST);
    }
}

// round 8
// speedup vs baseline: 2.4377x; 2.4377x over previous
#include <cuda_runtime.h>
#include <cuda_bf16.h>
#include <cstdint>
#include <math.h>

// ---------------- problem constants ----------------
#define TT   50
#define BB   2048
#define SST  256      // STATE
#define AAC  32       // ACTION
#define BEL  1024     // BELIEF
#define HID  1024     // HIDDEN
#define EMB  1024     // EMBED
#define KSA  320      // padded STATE+ACTION (288 -> 320, zero pad)

// ================= scratch (device globals; no allocation allowed) =================
// bf16 hi/lo weight copies (converted once per launch)
__device__ __align__(16) __nv_bfloat16 g_Wsa_h[1024 * KSA],  g_Wsa_l[1024 * KSA];
__device__ __align__(16) __nv_bfloat16 g_Wih_h[3072 * 1024], g_Wih_l[3072 * 1024];
__device__ __align__(16) __nv_bfloat16 g_Whh_h[3072 * 1024], g_Whh_l[3072 * 1024];
__device__ __align__(16) __nv_bfloat16 g_Wpb_h[1024 * 1024], g_Wpb_l[1024 * 1024];
__device__ __align__(16) __nv_bfloat16 g_Wps_h[512 * 1024],  g_Wps_l[512 * 1024];
__device__ __align__(16) __nv_bfloat16 g_Wqb_h[1024 * 2048], g_Wqb_l[1024 * 2048];
__device__ __align__(16) __nv_bfloat16 g_Wqs_h[512 * 1024],  g_Wqs_l[512 * 1024];
// bf16 hi/lo activations
__device__ __align__(16) __nv_bfloat16 g_Asa_h[BB * KSA],  g_Asa_l[BB * KSA];   // [state|action|pad]
__device__ __align__(16) __nv_bfloat16 g_rnn_h[BB * BEL],  g_rnn_l[BB * BEL];
__device__ __align__(16) __nv_bfloat16 g_bel_h[BB * BEL],  g_bel_l[BB * BEL];
__device__ __align__(16) __nv_bfloat16 g_Aqb_h[BB * 2048], g_Aqb_l[BB * 2048];  // [belief|obs]
__device__ __align__(16) __nv_bfloat16 g_ph_h[BB * HID],   g_ph_l[BB * HID];
__device__ __align__(16) __nv_bfloat16 g_qh_h[BB * HID],   g_qh_l[BB * HID];
// fp32 scratch
__device__ __align__(16) float g_gi[BB * 3 * BEL];
__device__ __align__(16) float g_gh[BB * 3 * BEL];
__device__ __align__(16) float g_pout[BB * 2 * SST];
__device__ __align__(16) float g_qout[BB * 2 * SST];

// ================= low-level helpers (all sm_80-baseline PTX) =================
__device__ __forceinline__ uint32_t smem_u32(const void* p) {
    uint32_t a;
    asm("{ .reg .u64 t; cvta.to.shared.u64 t, %1; cvt.u32.u64 %0, t; }" : "=r"(a) : "l"(p));
    return a;
}
__device__ __forceinline__ void cp16(uint32_t dst, const void* src) {
    asm volatile("cp.async.cg.shared.global [%0], [%1], 16;" :: "r"(dst), "l"(src));
}
#define CP_COMMIT()  asm volatile("cp.async.commit_group;" ::: "memory")
#define CP_WAIT1()   asm volatile("cp.async.wait_group 1;" ::: "memory")

__device__ __forceinline__ void ldsm4(uint32_t* r, uint32_t addr) {
    asm volatile("ldmatrix.sync.aligned.m8n8.x4.shared.b16 {%0,%1,%2,%3}, [%4];"
                 : "=r"(r[0]), "=r"(r[1]), "=r"(r[2]), "=r"(r[3]) : "r"(addr));
}
__device__ __forceinline__ void mma16816(float* c, const uint32_t* a, uint32_t b0, uint32_t b1) {
    asm volatile(
        "mma.sync.aligned.m16n8k16.row.col.f32.bf16.bf16.f32 "
        "{%0,%1,%2,%3}, {%4,%5,%6,%7}, {%8,%9}, {%0,%1,%2,%3};"
        : "+f"(c[0]), "+f"(c[1]), "+f"(c[2]), "+f"(c[3])
        : "r"(a[0]), "r"(a[1]), "r"(a[2]), "r"(a[3]), "r"(b0), "r"(b1));
}

// ================= warp-MMA split-bf16 GEMM =================
// C[2048, N] = act( A @ W^T + bias ), A=[2048,K] bf16 hi/lo, W=[N,K] bf16 hi/lo.
// 3-term: Ah*Wh + Ah*Wl + Al*Wh, fp32 accumulators.
// CTA tile 128x128, 8 warps (4M x 2N), warp tile 32x64, BK=32, 3-stage cp.async.
#define LDS     40                       // smem row stride in bf16 (32 + 8 pad)
#define TSE     (128 * LDS)              // tile stride, elems (5120)
#define TSB     (TSE * 2)                // tile stride, bytes (10240)
#define STAGE_B (4u * TSB)               // Ah, Al, Wh, Wl  (40960 B)
#define NSTAGE  3
#define SMEM_SZ (NSTAGE * STAGE_B)       // 122880 B

__device__ __forceinline__ void load_stage(uint32_t sbase,
    const __nv_bfloat16* __restrict__ Ah, const __nv_bfloat16* __restrict__ Al,
    const __nv_bfloat16* __restrict__ Wh, const __nv_bfloat16* __restrict__ Wl,
    int row0, int col0, int lda, int ldw, int kk, int tid)
{
    const __nv_bfloat16* srcs[4] = {Ah, Al, Wh, Wl};
    const int r0s[4] = {row0, row0, col0, col0};
    const int lds_[4] = {lda, lda, ldw, ldw};
#pragma unroll
    for (int t = 0; t < 4; t++) {
        uint32_t tb = sbase + (uint32_t)t * TSB;
#pragma unroll
        for (int i = 0; i < 2; i++) {
            int ch = i * 256 + tid;
            int r = ch >> 2, c4 = ch & 3;
            const void* src = srcs[t] + (size_t)(r0s[t] + r) * lds_[t] + kk + c4 * 8;
            cp16(tb + (uint32_t)(r * (LDS * 2) + c4 * 16), src);
        }
    }
}

template <bool RELU, bool BF16OUT>
__global__ __launch_bounds__(256, 1)
void mma_gemm(const __nv_bfloat16* __restrict__ Ah, const __nv_bfloat16* __restrict__ Al, int lda,
              const __nv_bfloat16* __restrict__ Wh, const __nv_bfloat16* __restrict__ Wl, int ldw,
              const float* __restrict__ bias, int N, int K,
              float* __restrict__ C, __nv_bfloat16* __restrict__ Ch, __nv_bfloat16* __restrict__ Cl)
{
    extern __shared__ char smem_raw[];
    const uint32_t sb0 = smem_u32(smem_raw);

    const int tid = threadIdx.x;
    const int lane = tid & 31, wid = tid >> 5;
    const int wm = wid & 3, wn = wid >> 2;          // 4 x 2 warp grid
    const int row0 = blockIdx.y * 128, col0 = blockIdx.x * 128;

    float acc[2][8][4];
#pragma unroll
    for (int a = 0; a < 2; a++)
#pragma unroll
        for (int b = 0; b < 8; b++)
#pragma unroll
            for (int c = 0; c < 4; c++) acc[a][b][c] = 0.0f;

    const int NC = K / 32;

    // prefetch stages 0,1
    load_stage(sb0,           Ah, Al, Wh, Wl, row0, col0, lda, ldw, 0,  tid); CP_COMMIT();
    load_stage(sb0 + STAGE_B, Ah, Al, Wh, Wl, row0, col0, lda, ldw, 32, tid); CP_COMMIT();

    const int lrow = lane & 15;
    const int lcol = (lane >> 4) << 3;

    for (int c = 0; c < NC; c++) {
        CP_WAIT1();
        __syncthreads();

        // issue loads for stage c+2 (overwrites buffer computed at iter c-1)
        int pf = c + 2;
        if (pf < NC)
            load_stage(sb0 + (uint32_t)(pf % NSTAGE) * STAGE_B,
                       Ah, Al, Wh, Wl, row0, col0, lda, ldw, pf * 32, tid);
        CP_COMMIT();

        const uint32_t st = sb0 + (uint32_t)(c % NSTAGE) * STAGE_B;
#pragma unroll
        for (int k16 = 0; k16 < 32; k16 += 16) {
            uint32_t ah[2][4], al[2][4], wh[4][4], wl[4][4];
#pragma unroll
            for (int mt = 0; mt < 2; mt++) {
                uint32_t ra = (uint32_t)((wm * 32 + mt * 16 + lrow) * LDS + k16 + lcol) * 2;
                ldsm4(ah[mt], st + ra);
                ldsm4(al[mt], st + TSB + ra);
            }
#pragma unroll
            for (int g = 0; g < 4; g++) {
                uint32_t rb = (uint32_t)((wn * 64 + g * 16 + lrow) * LDS + k16 + lcol) * 2;
                ldsm4(wh[g], st + 2 * TSB + rb);
                ldsm4(wl[g], st + 3 * TSB + rb);
            }
#pragma unroll
            for (int mt = 0; mt < 2; mt++)
#pragma unroll
                for (int g = 0; g < 4; g++)
#pragma unroll
                    for (int h = 0; h < 2; h++) {
                        float* cc = acc[mt][g * 2 + h];
                        mma16816(cc, ah[mt], wh[g][h], wh[g][h + 2]);
                        mma16816(cc, ah[mt], wl[g][h], wl[g][h + 2]);
                        mma16816(cc, al[mt], wh[g][h], wh[g][h + 2]);
                    }
        }
        __syncthreads();
    }

    // ---- epilogue ----
    const int gid = lane >> 2, tig = lane & 3;
#pragma unroll
    for (int mt = 0; mt < 2; mt++) {
        const int ra = row0 + wm * 32 + mt * 16 + gid;
#pragma unroll
        for (int nt = 0; nt < 8; nt++) {
            const int col = col0 + wn * 64 + nt * 8 + tig * 2;
            const float b0 = bias[col], b1 = bias[col + 1];
            const float* cc = acc[mt][nt];
#pragma unroll
            for (int half = 0; half < 2; half++) {
                const int r = ra + half * 8;
                float v0 = cc[half * 2 + 0] + b0;
                float v1 = cc[half * 2 + 1] + b1;
                if (RELU) { v0 = fmaxf(v0, 0.0f); v1 = fmaxf(v1, 0.0f); }
                const size_t o = (size_t)r * N + col;
                if (BF16OUT) {
                    __nv_bfloat16 h0 = __float2bfloat16(v0);
                    __nv_bfloat16 h1 = __float2bfloat16(v1);
                    Ch[o] = h0; Ch[o + 1] = h1;
                    Cl[o]     = __float2bfloat16(v0 - __bfloat162float(h0));
                    Cl[o + 1] = __float2bfloat16(v1 - __bfloat162float(h1));
                } else {
                    C[o] = v0; C[o + 1] = v1;
                }
            }
        }
    }
}

// ================= elementwise kernels =================
__device__ __forceinline__ void bf_split(float x, __nv_bfloat16& h, __nv_bfloat16& l) {
    h = __float2bfloat16(x);
    l = __float2bfloat16(x - __bfloat162float(h));
}

// fp32 [R,C] (srcld) -> bf16 hi/lo at [r, dstoff + c] (dstld)
__global__ void conv_split(const float* __restrict__ src, int srcld, int C,
                           __nv_bfloat16* __restrict__ hi, __nv_bfloat16* __restrict__ lo,
                           int dstld, int dstoff, int total)
{
    int i = blockIdx.x * blockDim.x + threadIdx.x;
    if (i >= total) return;
    int r = i / C, c = i - r * C;
    float x = src[(size_t)r * srcld + c];
    __nv_bfloat16 h, l; bf_split(x, h, l);
    size_t d = (size_t)r * dstld + dstoff + c;
    hi[d] = h; lo[d] = l;
}

__global__ void gru_combine(const float* __restrict__ gi, const float* __restrict__ gh,
                            const float* __restrict__ hprev, float* __restrict__ hout,
                            __nv_bfloat16* __restrict__ bel_h, __nv_bfloat16* __restrict__ bel_l,
                            __nv_bfloat16* __restrict__ qb_h,  __nv_bfloat16* __restrict__ qb_l)
{
    int i = blockIdx.x * blockDim.x + threadIdx.x;
    if (i >= BB * BEL) return;
    int b = i >> 10, c = i & 1023;
    const float* gib = gi + (size_t)b * 3 * BEL;
    const float* ghb = gh + (size_t)b * 3 * BEL;
    float ir = gib[c],           hr = ghb[c];
    float iz = gib[BEL + c],     hz = ghb[BEL + c];
    float in = gib[2 * BEL + c], hn = ghb[2 * BEL + c];
    float r = 1.0f / (1.0f + expf(-(ir + hr)));
    float z = 1.0f / (1.0f + expf(-(iz + hz)));
    float n = tanhf(in + r * hn);
    float h = (1.0f - z) * n + z * hprev[i];
    hout[i] = h;
    __nv_bfloat16 bh, bl; bf_split(h, bh, bl);
    bel_h[i] = bh; bel_l[i] = bl;
    size_t q = (size_t)b * 2048 + c;
    qb_h[q] = bh; qb_l[q] = bl;
}

__global__ void head_epi(const float* __restrict__ hout, const float* __restrict__ noise,
                         float* __restrict__ o_state, float* __restrict__ o_mean,
                         float* __restrict__ o_std,
                         __nv_bfloat16* __restrict__ sa_h, __nv_bfloat16* __restrict__ sa_l)
{
    int i = blockIdx.x * blockDim.x + threadIdx.x;
    if (i >= BB * SST) return;
    int b = i >> 8, c = i & 255;
    float m  = hout[(size_t)b * 2 * SST + c];
    float lg = hout[(size_t)b * 2 * SST + SST + c];
    float y  = expf(lg);
    float sp = (y > 20.0f) ? y : log1pf(expf(y));
    float sd = sp + 0.1f;
    float st = m + sd * noise[i];
    o_mean[i] = m; o_std[i] = sd; o_state[i] = st;
    if (sa_h) {
        __nv_bfloat16 h, l; bf_split(st, h, l);
        size_t d = (size_t)b * KSA + c;
        sa_h[d] = h; sa_l[d] = l;
    }
}

// ================= host dispatch =================
static inline void tcgemm(const __nv_bfloat16* Ah, const __nv_bfloat16* Al, int lda,
                          const __nv_bfloat16* Wh, const __nv_bfloat16* Wl, int ldw,
                          const float* bias, int N, int K,
                          float* C, __nv_bfloat16* Ch, __nv_bfloat16* Cl, bool relu_bf16)
{
    dim3 grid(N / 128, BB / 128);
    if (relu_bf16)
        mma_gemm<true, true><<<grid, 256, SMEM_SZ>>>(Ah, Al, lda, Wh, Wl, ldw, bias, N, K, C, Ch, Cl);
    else
        mma_gemm<false, false><<<grid, 256, SMEM_SZ>>>(Ah, Al, lda, Wh, Wl, ldw, bias, N, K, C, Ch, Cl);
}

static inline void conv(const float* src, int R, int C, int srcld,
                        __nv_bfloat16* h, __nv_bfloat16* l, int dstld, int off)
{
    int total = R * C;
    conv_split<<<(total + 255) / 256, 256>>>(src, srcld, C, h, l, dstld, off, total);
}

extern "C" void kernel_launch(void* const* d_in, const int* in_sizes, int n_in,
                              void* d_out, int out_size)
{
    const float* prev_state   = (const float*)d_in[0];
    const float* actions      = (const float*)d_in[1];
    const float* prev_belief  = (const float*)d_in[2];
    const float* observations = (const float*)d_in[3];
    const float* prior_noise  = (const float*)d_in[4];
    const float* post_noise   = (const float*)d_in[5];
    const float* W_sa = (const float*)d_in[6];
    const float* b_sa = (const float*)d_in[7];
    const float* W_ih = (const float*)d_in[8];
    const float* W_hh = (const float*)d_in[9];
    const float* b_ih = (const float*)d_in[10];
    const float* b_hh = (const float*)d_in[11];
    const float* W_pb = (const float*)d_in[12];
    const float* b_pb = (const float*)d_in[13];
    const float* W_ps = (const float*)d_in[14];
    const float* b_ps = (const float*)d_in[15];
    const float* W_qb = (const float*)d_in[16];
    const float* b_qb = (const float*)d_in[17];
    const float* W_qs = (const float*)d_in[18];
    const float* b_qs = (const float*)d_in[19];

    float* out = (float*)d_out;
    float* out_bel  = out;
    float* out_ps   = out_bel  + (size_t)TT * BB * BEL;
    float* out_pm   = out_ps   + (size_t)TT * BB * SST;
    float* out_pstd = out_pm   + (size_t)TT * BB * SST;
    float* out_qs   = out_pstd + (size_t)TT * BB * SST;
    float* out_qm   = out_qs   + (size_t)TT * BB * SST;
    float* out_qstd = out_qm   + (size_t)TT * BB * SST;

    cudaFuncSetAttribute(mma_gemm<true, true>,   cudaFuncAttributeMaxDynamicSharedMemorySize, SMEM_SZ);
    cudaFuncSetAttribute(mma_gemm<false, false>, cudaFuncAttributeMaxDynamicSharedMemorySize, SMEM_SZ);

    // resolve scratch symbols (capture-safe)
    __nv_bfloat16 *Wsa_h, *Wsa_l, *Wih_h, *Wih_l, *Whh_h, *Whh_l, *Wpb_h, *Wpb_l,
                  *Wps_h, *Wps_l, *Wqb_h, *Wqb_l, *Wqs_h, *Wqs_l,
                  *Asa_h, *Asa_l, *rnn_h, *rnn_l, *bel_h, *bel_l,
                  *Aqb_h, *Aqb_l, *ph_h, *ph_l, *qh_h, *qh_l;
    float *gi, *gh, *pout, *qout;
    cudaGetSymbolAddress((void**)&Wsa_h, g_Wsa_h); cudaGetSymbolAddress((void**)&Wsa_l, g_Wsa_l);
    cudaGetSymbolAddress((void**)&Wih_h, g_Wih_h); cudaGetSymbolAddress((void**)&Wih_l, g_Wih_l);
    cudaGetSymbolAddress((void**)&Whh_h, g_Whh_h); cudaGetSymbolAddress((void**)&Whh_l, g_Whh_l);
    cudaGetSymbolAddress((void**)&Wpb_h, g_Wpb_h); cudaGetSymbolAddress((void**)&Wpb_l, g_Wpb_l);
    cudaGetSymbolAddress((void**)&Wps_h, g_Wps_h); cudaGetSymbolAddress((void**)&Wps_l, g_Wps_l);
    cudaGetSymbolAddress((void**)&Wqb_h, g_Wqb_h); cudaGetSymbolAddress((void**)&Wqb_l, g_Wqb_l);
    cudaGetSymbolAddress((void**)&Wqs_h, g_Wqs_h); cudaGetSymbolAddress((void**)&Wqs_l, g_Wqs_l);
    cudaGetSymbolAddress((void**)&Asa_h, g_Asa_h); cudaGetSymbolAddress((void**)&Asa_l, g_Asa_l);
    cudaGetSymbolAddress((void**)&rnn_h, g_rnn_h); cudaGetSymbolAddress((void**)&rnn_l, g_rnn_l);
    cudaGetSymbolAddress((void**)&bel_h, g_bel_h); cudaGetSymbolAddress((void**)&bel_l, g_bel_l);
    cudaGetSymbolAddress((void**)&Aqb_h, g_Aqb_h); cudaGetSymbolAddress((void**)&Aqb_l, g_Aqb_l);
    cudaGetSymbolAddress((void**)&ph_h,  g_ph_h);  cudaGetSymbolAddress((void**)&ph_l,  g_ph_l);
    cudaGetSymbolAddress((void**)&qh_h,  g_qh_h);  cudaGetSymbolAddress((void**)&qh_l,  g_qh_l);
    cudaGetSymbolAddress((void**)&gi,   g_gi);   cudaGetSymbolAddress((void**)&gh,   g_gh);
    cudaGetSymbolAddress((void**)&pout, g_pout); cudaGetSymbolAddress((void**)&qout, g_qout);

    // zero padded buffers (pad columns stay zero; real columns rewritten each step)
    cudaMemsetAsync(Asa_h, 0, (size_t)BB * KSA * sizeof(__nv_bfloat16));
    cudaMemsetAsync(Asa_l, 0, (size_t)BB * KSA * sizeof(__nv_bfloat16));
    cudaMemsetAsync(Wsa_h, 0, (size_t)1024 * KSA * sizeof(__nv_bfloat16));
    cudaMemsetAsync(Wsa_l, 0, (size_t)1024 * KSA * sizeof(__nv_bfloat16));

    // convert weights once per launch
    conv(W_sa, 1024, 288, 288, Wsa_h, Wsa_l, KSA, 0);
    conv(W_ih, 3072, 1024, 1024, Wih_h, Wih_l, 1024, 0);
    conv(W_hh, 3072, 1024, 1024, Whh_h, Whh_l, 1024, 0);
    conv(W_pb, 1024, 1024, 1024, Wpb_h, Wpb_l, 1024, 0);
    conv(W_ps,  512, 1024, 1024, Wps_h, Wps_l, 1024, 0);
    conv(W_qb, 1024, 2048, 2048, Wqb_h, Wqb_l, 2048, 0);
    conv(W_qs,  512, 1024, 1024, Wqs_h, Wqs_l, 1024, 0);

    // t=0 carries
    conv(prev_state, BB, SST, SST, Asa_h, Asa_l, KSA, 0);
    conv(prev_belief, BB, BEL, BEL, bel_h, bel_l, BEL, 0);

    const int EW_T = 256;
    const int nb_bel  = (BB * BEL + EW_T - 1) / EW_T;
    const int nb_head = (BB * SST + EW_T - 1) / EW_T;

    for (int t = 0; t < TT; t++) {
        const float* a_t  = actions      + (size_t)t * BB * AAC;
        const float* o_t  = observations + (size_t)t * BB * EMB;
        const float* pn_t = prior_noise  + (size_t)t * BB * SST;
        const float* qn_t = post_noise   + (size_t)t * BB * SST;
        const float* bel_prev_f32 = (t == 0) ? prev_belief
                                             : out_bel + (size_t)(t - 1) * BB * BEL;
        float* bel_t = out_bel + (size_t)t * BB * BEL;

        // action slice -> packed A_sa cols [256..288)
        conv(a_t, BB, AAC, AAC, Asa_h, Asa_l, KSA, SST);

        // 1. rnn_in = relu([state|action] @ W_sa^T + b_sa) -> bf16 pair
        tcgemm(Asa_h, Asa_l, KSA, Wsa_h, Wsa_l, KSA, b_sa, BEL, KSA,
               nullptr, rnn_h, rnn_l, true);

        // 2. GRU gates (fp32 out)
        tcgemm(rnn_h, rnn_l, BEL, Wih_h, Wih_l, BEL, b_ih, 3 * BEL, BEL,
               gi, nullptr, nullptr, false);
        tcgemm(bel_h, bel_l, BEL, Whh_h, Whh_l, BEL, b_hh, 3 * BEL, BEL,
               gh, nullptr, nullptr, false);
        gru_combine<<<nb_bel, EW_T>>>(gi, gh, bel_prev_f32, bel_t,
                                      bel_h, bel_l, Aqb_h, Aqb_l);

        // 3. prior head
        tcgemm(bel_h, bel_l, BEL, Wpb_h, Wpb_l, BEL, b_pb, HID, BEL,
               nullptr, ph_h, ph_l, true);
        tcgemm(ph_h, ph_l, HID, Wps_h, Wps_l, HID, b_ps, 2 * SST, HID,
               pout, nullptr, nullptr, false);
        head_epi<<<nb_head, EW_T>>>(pout, pn_t,
                                    out_ps   + (size_t)t * BB * SST,
                                    out_pm   + (size_t)t * BB * SST,
                                    out_pstd + (size_t)t * BB * SST,
                                    nullptr, nullptr);

        // 4. posterior head (obs into packed A_qb cols [1024..2048))
        conv(o_t, BB, EMB, EMB, Aqb_h, Aqb_l, 2048, BEL);
        tcgemm(Aqb_h, Aqb_l, 2048, Wqb_h, Wqb_l, 2048, b_qb, HID, 2048,
               nullptr, qh_h, qh_l, true);
        tcgemm(qh_h, qh_l, HID, Wqs_h, Wqs_l, HID, b_qs, 2 * SST, HID,
               qout, nullptr, nullptr, false);
        head_epi<<<nb_head, EW_T>>>(qout, qn_t,
                                    out_qs   + (size_t)t * BB * SST,
                                    out_qm   + (size_t)t * BB * SST,
                                    out_qstd + (size_t)t * BB * SST,
                                    Asa_h, Asa_l);  // next-step state
    }
}